// round 9
// baseline (speedup 1.0000x reference)
#include <cuda_runtime.h>

// Problem constants
#define NPG   61
#define NB    128
#define NNODE 7808         // NB*NPG
#define NE    468480       // NB * 61*60
#define EPG   3660
#define LQ    160
#define NF    64
#define HC    128

typedef unsigned long long ull;

// ---------------- f32x2 helpers ----------------
__device__ __forceinline__ ull pack2(float lo, float hi) {
    ull r; asm("mov.b64 %0, {%1, %2};" : "=l"(r) : "f"(lo), "f"(hi)); return r;
}
__device__ __forceinline__ float2 u2f(ull u) {
    float2 v; asm("mov.b64 {%0, %1}, %2;" : "=f"(v.x), "=f"(v.y) : "l"(u)); return v;
}
__device__ __forceinline__ ull fma2(ull a, ull b, ull c) {
    ull d; asm("fma.rn.f32x2 %0, %1, %2, %3;" : "=l"(d) : "l"(a), "l"(b), "l"(c)); return d;
}

// ---------------- device scratch ----------------
__device__ float      d_At[NB * 64 * 64];     // TRANSPOSED adjacency At[g][s][d]
__device__ ull        d_w1u[64 * 5 * 64];     // conv1 weights dup-packed as ull
__device__ float      d_w2t[64 * 3 * 64];     // conv2 weights transposed
__device__ ulonglong2 d_gw0u[16 * HC];
__device__ ulonglong2 d_gw1u[32 * HC];
__device__ ulonglong2 d_gw2u[32 * HC];
__device__ float      d_H0[NNODE * NF];
__device__ float      d_G1[NNODE * HC];
__device__ float      d_G2[NNODE * HC];
__device__ float      d_HW[NNODE * HC];
__device__ float      d_P[NB * NPG * HC];     // lin0 partials, [g][node][j]
__device__ float      d_bp1s[61 * NF], d_bp1q[61 * NF];
__device__ float      d_bp2s[4 * NB * HC], d_bp2q[4 * NB * HC];
__device__ float      d_sc1[NF], d_sh1[NF];
__device__ float      d_sc2[HC], d_sh2[HC];

// ---------------- K0: zero At, transpose/pack weights ----------------
__global__ void k_prep(const float* __restrict__ w1, const float* __restrict__ w2,
                       const float* __restrict__ gw0, const float* __restrict__ gw1,
                       const float* __restrict__ gw2) {
    int t0 = blockIdx.x * blockDim.x + threadIdx.x;
    int stride = gridDim.x * blockDim.x;
    for (int i = t0; i < NB * 64 * 64; i += stride) d_At[i] = 0.f;
    for (int i = t0; i < 64 * 5 * 64; i += stride) {
        int f = i & 63; int r = i >> 6; int k = r % 5; int c = r / 5;
        float v = w1[(f * 64 + c) * 5 + k];
        d_w1u[i] = pack2(v, v);
    }
    for (int i = t0; i < 64 * 3 * 64; i += stride) {
        int f = i & 63; int r = i >> 6; int k = r % 3; int c = r / 3;
        d_w2t[i] = w2[(f * 64 + c) * 3 + k];
    }
    for (int i = t0; i < 16 * HC; i += stride) {
        int j = i & (HC - 1); int kq = i >> 7;
        ulonglong2 u;
        u.x = pack2(gw0[(4 * kq) * HC + j], gw0[(4 * kq + 1) * HC + j]);
        u.y = pack2(gw0[(4 * kq + 2) * HC + j], gw0[(4 * kq + 3) * HC + j]);
        d_gw0u[i] = u;
    }
    for (int i = t0; i < 32 * HC; i += stride) {
        int j = i & (HC - 1); int kq = i >> 7;
        ulonglong2 u, v;
        u.x = pack2(gw1[(4 * kq) * HC + j], gw1[(4 * kq + 1) * HC + j]);
        u.y = pack2(gw1[(4 * kq + 2) * HC + j], gw1[(4 * kq + 3) * HC + j]);
        d_gw1u[i] = u;
        v.x = pack2(gw2[(4 * kq) * HC + j], gw2[(4 * kq + 1) * HC + j]);
        v.y = pack2(gw2[(4 * kq + 2) * HC + j], gw2[(4 * kq + 3) * HC + j]);
        d_gw2u[i] = v;
    }
}

// ---------------- K1: edges ----------------
__global__ void __launch_bounds__(1024) k_edges(
        const float* __restrict__ ef, const int* __restrict__ ei,
        const float* __restrict__ eww, const float* __restrict__ ewb,
        float* __restrict__ out) {
    int w = threadIdx.x >> 5;
    int l = threadIdx.x & 31;
    int i0 = blockIdx.x * 32;
    int g0 = blockIdx.y * 32;
    __shared__ float ts[32][33];

    int g = g0 + w;
    int i = i0 + l;
    float v = 0.f;
    if (i < EPG) {
        int e = g * EPG + i;
        v = tanhf(fmaf(ef[e * 3 + 0], eww[0],
                 fmaf(ef[e * 3 + 1], eww[1],
                 fmaf(ef[e * 3 + 2], eww[2], ewb[0]))));
        int s = ei[e];
        int d = ei[NE + e];
        int g2 = d / NPG;
        int dl = d - g2 * NPG;
        int sl = s - g2 * NPG;
        d_At[(g2 * 64 + sl) * 64 + dl] = v;
    }
    ts[w][l] = v;
    __syncthreads();
    int iw = i0 + w;
    if (iw < EPG) out[NB * 4 + iw * NB + g0 + l] = ts[l][w];
}

// ---------------- K2: conv pipeline. Block = 64 thr = 2 warps = 2 nodes.
// Warp handles one node; lane l owns channels f0=2l, f1=2l+1.
// p0 stored pre-paired (pe/po) so conv1 is pure LDS.64 + LDG.128 + FFMA2,
// with every shared-operand load serving TWO output channels.
__global__ void __launch_bounds__(64) k_conv(
        const float* __restrict__ x,
        const float* __restrict__ w0, const float* __restrict__ b0,
        const float* __restrict__ b1, const float* __restrict__ b2) {
    int warp = threadIdx.x >> 5;
    int l = threadIdx.x & 31;
    int n = blockIdx.x * 2 + warp;
    int f0 = 2 * l, f1 = f0 + 1;

    __shared__ __align__(16) float xs[2][LQ];
    __shared__ __align__(16) ull   pes[2][64][13];
    __shared__ __align__(16) float pof[2][64][24];
    __shared__ float p1s[2][64][3];

    for (int i = l; i < LQ; i += 32) xs[warp][i] = x[n * LQ + i];

    ull w0da[7], w0db[7];
#pragma unroll
    for (int k = 0; k < 7; k++) {
        float wa = w0[f0 * 7 + k], wb = w0[f1 * 7 + k];
        w0da[k] = pack2(wa, wa);
        w0db[k] = pack2(wb, wb);
    }
    float b0a = b0[f0], b0b = b0[f1];
    ull b0da = pack2(b0a, b0a), b0db = pack2(b0b, b0b);

    // borders
    pes[warp][f0][0] = 0ull;  pes[warp][f0][12] = 0ull;
    pes[warp][f1][0] = 0ull;  pes[warp][f1][12] = 0ull;
    pof[warp][f0][0] = 0.f;   pof[warp][f0][23] = 0.f;
    pof[warp][f1][0] = 0.f;   pof[warp][f1][23] = 0.f;
    __syncwarp();

    // conv0 (k=7) + relu + maxpool7 for both channels; xq shared across f0/f1
#pragma unroll 1
    for (int jp = 0; jp < 11; jp++) {
        const float2* xr = reinterpret_cast<const float2*>(&xs[warp][14 * jp]);
        float a[20];
#pragma unroll
        for (int m = 0; m < 10; m++) { float2 t = xr[m]; a[2 * m] = t.x; a[2 * m + 1] = t.y; }
        ull xq[13];
#pragma unroll
        for (int q = 0; q < 13; q++) xq[q] = pack2(a[q], a[q + 7]);
        ull s0[7], s1[7];
#pragma unroll
        for (int u = 0; u < 7; u++) { s0[u] = b0da; s1[u] = b0db; }
#pragma unroll
        for (int k = 0; k < 7; k++)
#pragma unroll
            for (int u = 0; u < 7; u++) {
                s0[u] = fma2(xq[u + k], w0da[k], s0[u]);
                s1[u] = fma2(xq[u + k], w0db[k], s1[u]);
            }
        float m0a = -1e30f, m1a = -1e30f, m0b = -1e30f, m1b = -1e30f;
#pragma unroll
        for (int u = 0; u < 7; u++) {
            float2 va = u2f(s0[u]);
            m0a = fmaxf(m0a, va.x); m1a = fmaxf(m1a, va.y);
            float2 vb = u2f(s1[u]);
            m0b = fmaxf(m0b, vb.x); m1b = fmaxf(m1b, vb.y);
        }
        m0a = fmaxf(m0a, 0.f); m1a = fmaxf(m1a, 0.f);
        m0b = fmaxf(m0b, 0.f); m1b = fmaxf(m1b, 0.f);
        pes[warp][f0][jp + 1] = pack2(m0a, m1a);
        pes[warp][f1][jp + 1] = pack2(m0b, m1b);
        pof[warp][f0][2 * jp + 1] = m0a;  pof[warp][f0][2 * jp + 2] = m1a;
        pof[warp][f1][2 * jp + 1] = m0b;  pof[warp][f1][2 * jp + 2] = m1b;
    }
    __syncwarp();

    // conv1 (k=5, pad 2): each loaded p0 row serves both output channels
    float b1a = b1[f0], b1b = b1[f1];
    ull accA[11], accB[11];
#pragma unroll
    for (int j = 0; j < 11; j++) { accA[j] = pack2(b1a, b1a); accB[j] = pack2(b1b, b1b); }

#pragma unroll 1
    for (int c = 0; c < 64; c++) {
        ull pe[13];
#pragma unroll
        for (int m = 0; m < 13; m++) pe[m] = pes[warp][c][m];
        ull po[12];
        const ull* pou = reinterpret_cast<const ull*>(&pof[warp][c][0]);
#pragma unroll
        for (int m = 0; m < 12; m++) po[m] = pou[m];
        const ull* wp = &d_w1u[c * 5 * 64 + f0];
        ulonglong2 wk0 = *reinterpret_cast<const ulonglong2*>(wp);
        ulonglong2 wk1 = *reinterpret_cast<const ulonglong2*>(wp + 64);
        ulonglong2 wk2 = *reinterpret_cast<const ulonglong2*>(wp + 128);
        ulonglong2 wk3 = *reinterpret_cast<const ulonglong2*>(wp + 192);
        ulonglong2 wk4 = *reinterpret_cast<const ulonglong2*>(wp + 256);
#pragma unroll
        for (int j = 0; j < 11; j++) {
            accA[j] = fma2(pe[j],     wk0.x, accA[j]);
            accB[j] = fma2(pe[j],     wk0.y, accB[j]);
            accA[j] = fma2(po[j],     wk1.x, accA[j]);
            accB[j] = fma2(po[j],     wk1.y, accB[j]);
            accA[j] = fma2(pe[j + 1], wk2.x, accA[j]);
            accB[j] = fma2(pe[j + 1], wk2.y, accB[j]);
            accA[j] = fma2(po[j + 1], wk3.x, accA[j]);
            accB[j] = fma2(po[j + 1], wk3.y, accB[j]);
            accA[j] = fma2(pe[j + 2], wk4.x, accA[j]);
            accB[j] = fma2(pe[j + 2], wk4.y, accB[j]);
        }
    }
    // relu + maxpool7 (3 windows) for both channels
    {
        float acc[22];
#pragma unroll
        for (int j = 0; j < 11; j++) {
            float2 v = u2f(accA[j]);
            acc[2 * j] = v.x; acc[2 * j + 1] = v.y;
        }
#pragma unroll
        for (int j = 0; j < 3; j++) {
            float m = acc[7 * j];
#pragma unroll
            for (int u = 1; u < 7; u++) m = fmaxf(m, acc[7 * j + u]);
            p1s[warp][f0][j] = fmaxf(m, 0.f);
        }
#pragma unroll
        for (int j = 0; j < 11; j++) {
            float2 v = u2f(accB[j]);
            acc[2 * j] = v.x; acc[2 * j + 1] = v.y;
        }
#pragma unroll
        for (int j = 0; j < 3; j++) {
            float m = acc[7 * j];
#pragma unroll
            for (int u = 1; u < 7; u++) m = fmaxf(m, acc[7 * j + u]);
            p1s[warp][f1][j] = fmaxf(m, 0.f);
        }
    }
    __syncwarp();

    // conv2 (k=3, len 3 -> 1), both channels
    float sa = b2[f0], sb = b2[f1];
#pragma unroll 1
    for (int c = 0; c < 64; c++) {
        float p0v = p1s[warp][c][0], p1v = p1s[warp][c][1], p2v = p1s[warp][c][2];
        float2 wa = *reinterpret_cast<const float2*>(&d_w2t[(c * 3 + 0) * 64 + f0]);
        float2 wb = *reinterpret_cast<const float2*>(&d_w2t[(c * 3 + 1) * 64 + f0]);
        float2 wc = *reinterpret_cast<const float2*>(&d_w2t[(c * 3 + 2) * 64 + f0]);
        sa = fmaf(p0v, wa.x, sa); sb = fmaf(p0v, wa.y, sb);
        sa = fmaf(p1v, wb.x, sa); sb = fmaf(p1v, wb.y, sb);
        sa = fmaf(p2v, wc.x, sa); sb = fmaf(p2v, wc.y, sb);
    }
    *reinterpret_cast<float2*>(&d_H0[n * NF + f0]) = make_float2(sa, sb);
}

// ---------------- BN1 stats ----------------
__global__ void __launch_bounds__(256) k_bns1a() {
    int t = threadIdx.x;
    int c = t & 63;
    int grp = t >> 6;
    int gid = blockIdx.x * 4 + grp;
    float s = 0.f, q = 0.f;
    for (int n = gid; n < NNODE; n += 244) {
        float v = d_H0[n * NF + c];
        s += v; q += v * v;
    }
    __shared__ float ss[256], sq[256];
    ss[t] = s; sq[t] = q;
    __syncthreads();
    if (t < 64) {
        d_bp1s[blockIdx.x * 64 + t] = ss[t] + ss[64 + t] + ss[128 + t] + ss[192 + t];
        d_bp1q[blockIdx.x * 64 + t] = sq[t] + sq[64 + t] + sq[128 + t] + sq[192 + t];
    }
}
__global__ void __launch_bounds__(64) k_bns1b(const float* __restrict__ gg,
                                              const float* __restrict__ bb) {
    int c = threadIdx.x;
    float s = 0.f, q = 0.f;
    for (int b = 0; b < 61; b++) { s += d_bp1s[b * 64 + c]; q += d_bp1q[b * 64 + c]; }
    float mean = s / (float)NNODE;
    float var = q / (float)NNODE - mean * mean;
    float rs = rsqrtf(var + 1e-5f);
    d_sc1[c] = gg[c] * rs;
    d_sh1[c] = bb[c] - mean * gg[c] * rs;
}
__global__ void __launch_bounds__(128) k_bns2b(const float* __restrict__ gg,
                                               const float* __restrict__ bb) {
    int c = threadIdx.x;
    float s = 0.f, q = 0.f;
    for (int g = 0; g < 4 * NB; g++) { s += d_bp2s[g * HC + c]; q += d_bp2q[g * HC + c]; }
    float mean = s / (float)NNODE;
    float var = q / (float)NNODE - mean * mean;
    float rs = rsqrtf(var + 1e-5f);
    d_sc2[c] = gg[c] * rs;
    d_sh2[c] = bb[c] - mean * gg[c] * rs;
}

// ---------------- GNN phase A: hw = bn?(h) @ W + b. grid (NB, 4), 128 thr ----------------
template<int K, bool BN, int INSEL, int WSEL>
__global__ void __launch_bounds__(128) k_gnn_a(const float* __restrict__ bias) {
    const float* hin = (INSEL == 0) ? (const float*)d_H0
                     : (INSEL == 1) ? (const float*)d_G1 : (const float*)d_G2;
    const ulonglong2* Wu = (WSEL == 0) ? (const ulonglong2*)d_gw0u
                         : (WSEL == 1) ? (const ulonglong2*)d_gw1u : (const ulonglong2*)d_gw2u;
    int g = blockIdx.x;
    int qb = blockIdx.y;
    int n0 = qb * 16;
    int NR = (qb == 3) ? 13 : 16;
    int j = threadIdx.x;
    __shared__ __align__(16) float hs[16 * K];

    for (int idx = j; idx < 16 * K; idx += 128) {
        float v = 0.f;
        if (idx < NR * K) {
            v = hin[(g * 61 + n0) * K + idx];
            if (BN) { int c = idx & (K - 1); v = fmaf(v, d_sc1[c], d_sh1[c]); }
        }
        hs[idx] = v;
    }
    __syncthreads();

    ull acc[16];
#pragma unroll
    for (int n = 0; n < 16; n++) acc[n] = 0ull;
#pragma unroll 1
    for (int kq = 0; kq < K / 4; kq++) {
        ulonglong2 w = Wu[kq * HC + j];
#pragma unroll
        for (int n = 0; n < 16; n++) {
            ulonglong2 h2 = *reinterpret_cast<const ulonglong2*>(&hs[n * K + 4 * kq]);
            acc[n] = fma2(h2.x, w.x, acc[n]);
            acc[n] = fma2(h2.y, w.y, acc[n]);
        }
    }
    float bj = bias[j];
    for (int n = 0; n < NR; n++) {
        float2 v = u2f(acc[n]);
        d_HW[(g * 61 + n0 + n) * HC + j] = bj + v.x + v.y;
    }
}

// ---------------- GNN phase B: h' = A @ hw. grid (NB, 4), 128 thr ----------------
template<bool RELU, bool STATS, int OUTSEL>
__global__ void __launch_bounds__(128) k_gnn_b() {
    float* hout = (OUTSEL == 1) ? (float*)d_G1 : (float*)d_G2;
    int g = blockIdx.x;
    int qb = blockIdx.y;
    int doff = qb * 16;
    int ND = (qb == 3) ? 13 : 16;
    int j = threadIdx.x;
    __shared__ __align__(16) float hs[61 * HC];
    __shared__ __align__(16) float As2[61 * 20];

    for (int idx = j; idx < 61 * HC; idx += 128) hs[idx] = d_HW[g * 61 * HC + idx];
    for (int idx = j; idx < 61 * 16; idx += 128) {
        int s = idx >> 4, dd = idx & 15;
        As2[s * 20 + dd] = d_At[g * 4096 + s * 64 + doff + dd];
    }
    __syncthreads();

    ull acc[8];
#pragma unroll
    for (int p = 0; p < 8; p++) acc[p] = 0ull;
#pragma unroll 1
    for (int s = 0; s < 61; s++) {
        float v = hs[s * HC + j];
        ull v2 = pack2(v, v);
        const ulonglong2* ar = reinterpret_cast<const ulonglong2*>(&As2[s * 20]);
#pragma unroll
        for (int p = 0; p < 4; p++) {
            ulonglong2 a = ar[p];
            acc[2 * p]     = fma2(a.x, v2, acc[2 * p]);
            acc[2 * p + 1] = fma2(a.y, v2, acc[2 * p + 1]);
        }
    }
    float ssum = 0.f, sqsum = 0.f;
#pragma unroll
    for (int p = 0; p < 8; p++) {
        float2 r2 = u2f(acc[p]);
        int d0 = 2 * p, d1 = 2 * p + 1;
        if (d0 < ND) {
            float r = r2.x;
            if (STATS) { ssum += r; sqsum += r * r; }
            if (RELU) r = fmaxf(r, 0.f);
            hout[(g * 61 + doff + d0) * HC + j] = r;
        }
        if (d1 < ND) {
            float r = r2.y;
            if (STATS) { ssum += r; sqsum += r * r; }
            if (RELU) r = fmaxf(r, 0.f);
            hout[(g * 61 + doff + d1) * HC + j] = r;
        }
    }
    if (STATS) {
        d_bp2s[(g * 4 + qb) * HC + j] = ssum;
        d_bp2q[(g * 4 + qb) * HC + j] = sqsum;
    }
}

// ---------------- lin0: split-K over nodes. grid (61, 8), 128 thr ----------------
__global__ void __launch_bounds__(128) k_lin0(const float* __restrict__ W0) {
    int node = blockIdx.x;
    int gc = blockIdx.y;
    int j = threadIdx.x;
    __shared__ __align__(16) float vsT[HC * 20];
    float sc = d_sc2[j], sh = d_sh2[j];
#pragma unroll 1
    for (int q = 0; q < 16; q++) {
        int g = gc * 16 + q;
        vsT[j * 20 + q] = fmaf(d_G1[(g * 61 + node) * HC + j], sc, sh);
    }
    __syncthreads();
    ull acc[8];
#pragma unroll
    for (int p = 0; p < 8; p++) acc[p] = 0ull;
#pragma unroll 1
    for (int ch = 0; ch < HC; ch++) {
        float w = W0[(node * HC + ch) * HC + j];
        ull wd = pack2(w, w);
        const ulonglong2* vr = reinterpret_cast<const ulonglong2*>(&vsT[ch * 20]);
#pragma unroll
        for (int p = 0; p < 4; p++) {
            ulonglong2 v = vr[p];
            acc[2 * p]     = fma2(v.x, wd, acc[2 * p]);
            acc[2 * p + 1] = fma2(v.y, wd, acc[2 * p + 1]);
        }
    }
#pragma unroll
    for (int p = 0; p < 8; p++) {
        float2 v = u2f(acc[p]);
        int g0 = gc * 16 + 2 * p;
        d_P[(g0 * NPG + node) * HC + j] = v.x;
        d_P[((g0 + 1) * NPG + node) * HC + j] = v.y;
    }
}

// ---------------- head ----------------
__global__ void __launch_bounds__(128) k_head(const float* __restrict__ b0,
                                              const float* __restrict__ W1,
                                              const float* __restrict__ b1,
                                              const float* __restrict__ W2,
                                              const float* __restrict__ b2,
                                              float* __restrict__ out) {
    int g = blockIdx.x;
    int j = threadIdx.x;
    float z = b0[j];
    for (int node = 0; node < NPG; node++) z += d_P[(g * NPG + node) * HC + j];
    z = fmaxf(z, 0.f);
    __shared__ float z1[HC];
    z1[j] = z;
    __syncthreads();
    float a = b1[j];
    for (int k = 0; k < HC; k++) a = fmaf(z1[k], W1[k * HC + j], a);
    a = fmaxf(a, 0.f);
    __shared__ float z2[HC];
    z2[j] = a;
    __syncthreads();
    __shared__ float z3[4];
    if (j < 4) {
        float s = b2[j];
        for (int k = 0; k < HC; k++) s = fmaf(z2[k], W2[k * 4 + j], s);
        z3[j] = s;
    }
    __syncthreads();
    if (j == 0) {
        float m = fmaxf(fmaxf(z3[0], z3[1]), fmaxf(z3[2], z3[3]));
        float se = 0.f;
        for (int i = 0; i < 4; i++) se += expf(z3[i] - m);
        float l = logf(se);
        for (int i = 0; i < 4; i++) out[g * 4 + i] = z3[i] - m - l;
    }
}

// ---------------- launch ----------------
extern "C" void kernel_launch(void* const* d_in, const int* in_sizes, int n_in,
                              void* d_out, int out_size) {
    const float* x    = (const float*)d_in[0];
    const int*   ei   = (const int*)d_in[1];
    const float* ef   = (const float*)d_in[3];
    const float* cw0  = (const float*)d_in[4];
    const float* cb0  = (const float*)d_in[5];
    const float* cw1  = (const float*)d_in[6];
    const float* cb1  = (const float*)d_in[7];
    const float* cw2  = (const float*)d_in[8];
    const float* cb2  = (const float*)d_in[9];
    const float* bn1g = (const float*)d_in[10];
    const float* bn1b = (const float*)d_in[11];
    const float* gw0  = (const float*)d_in[12];
    const float* gb0  = (const float*)d_in[13];
    const float* gw1  = (const float*)d_in[14];
    const float* gb1  = (const float*)d_in[15];
    const float* gw2  = (const float*)d_in[16];
    const float* gb2  = (const float*)d_in[17];
    const float* bn2g = (const float*)d_in[18];
    const float* bn2b = (const float*)d_in[19];
    const float* lw0  = (const float*)d_in[20];
    const float* lb0  = (const float*)d_in[21];
    const float* lw1  = (const float*)d_in[22];
    const float* lb1  = (const float*)d_in[23];
    const float* lw2  = (const float*)d_in[24];
    const float* lb2  = (const float*)d_in[25];
    const float* eww  = (const float*)d_in[26];
    const float* ewb  = (const float*)d_in[27];
    float* out = (float*)d_out;

    k_prep<<<256, 256>>>(cw1, cw2, gw0, gw1, gw2);
    dim3 eg((EPG + 31) / 32, NB / 32);
    k_edges<<<eg, 1024>>>(ef, ei, eww, ewb, out);
    k_conv<<<NNODE / 2, 64>>>(x, cw0, cb0, cb1, cb2);
    k_bns1a<<<61, 256>>>();
    k_bns1b<<<1, 64>>>(bn1g, bn1b);
    dim3 gg(NB, 4);
    k_gnn_a< 64, true,  0, 0><<<gg, 128>>>(gb0);
    k_gnn_b<true,  false, 1><<<gg, 128>>>();
    k_gnn_a<128, false, 1, 1><<<gg, 128>>>(gb1);
    k_gnn_b<true,  false, 2><<<gg, 128>>>();
    k_gnn_a<128, false, 2, 2><<<gg, 128>>>(gb2);
    k_gnn_b<false, true,  1><<<gg, 128>>>();
    k_bns2b<<<1, 128>>>(bn2g, bn2b);
    dim3 lg(NPG, 8);
    k_lin0<<<lg, 128>>>(lw0);
    k_head<<<NB, 128>>>(lb0, lw1, lb1, lw2, lb2, out);
}

// round 11
// speedup vs baseline: 1.0628x; 1.0628x over previous
#include <cuda_runtime.h>

// Problem constants
#define NPG   61
#define NB    128
#define NNODE 7808         // NB*NPG
#define NE    468480       // NB * 61*60
#define EPG   3660
#define LQ    160
#define NF    64
#define HC    128

typedef unsigned long long ull;

// ---------------- f32x2 helpers ----------------
__device__ __forceinline__ ull pack2(float lo, float hi) {
    ull r; asm("mov.b64 %0, {%1, %2};" : "=l"(r) : "f"(lo), "f"(hi)); return r;
}
__device__ __forceinline__ float2 u2f(ull u) {
    float2 v; asm("mov.b64 {%0, %1}, %2;" : "=f"(v.x), "=f"(v.y) : "l"(u)); return v;
}
__device__ __forceinline__ ull fma2(ull a, ull b, ull c) {
    ull d; asm("fma.rn.f32x2 %0, %1, %2, %3;" : "=l"(d) : "l"(a), "l"(b), "l"(c)); return d;
}

// ---------------- device scratch ----------------
__device__ float      d_At[NB * 64 * 64];     // TRANSPOSED adjacency At[g][s][d]
__device__ ull        d_w1u[64 * 5 * 64];     // conv1 weights dup-packed as ull
__device__ float      d_w2t[64 * 3 * 64];     // conv2 weights transposed
__device__ ulonglong2 d_gw0u[16 * HC];
__device__ ulonglong2 d_gw1u[32 * HC];
__device__ ulonglong2 d_gw2u[32 * HC];
__device__ float      d_H0[NNODE * NF];
__device__ float      d_G1[NNODE * HC];
__device__ float      d_G2[NNODE * HC];
__device__ float      d_HW[NNODE * HC];
__device__ float      d_P[NB * NPG * HC];     // lin0 partials, [g][node][j]
__device__ float      d_bp1s[61 * NF], d_bp1q[61 * NF];
__device__ float      d_bp2s[2 * NB * HC], d_bp2q[2 * NB * HC];
__device__ float      d_sc1[NF], d_sh1[NF];
__device__ float      d_sc2[HC], d_sh2[HC];

// ---------------- K0a: zero adjacency ----------------
__global__ void k_prep_zero() {
    int t0 = blockIdx.x * blockDim.x + threadIdx.x;
    int stride = gridDim.x * blockDim.x;
    for (int i = t0; i < NB * 64 * 64; i += stride) d_At[i] = 0.f;
}

// ---------------- K0b: transpose/pack weights ----------------
__global__ void k_prep_w(const float* __restrict__ w1, const float* __restrict__ w2,
                         const float* __restrict__ gw0, const float* __restrict__ gw1,
                         const float* __restrict__ gw2) {
    int t0 = blockIdx.x * blockDim.x + threadIdx.x;
    int stride = gridDim.x * blockDim.x;
    for (int i = t0; i < 64 * 5 * 64; i += stride) {
        int f = i & 63; int r = i >> 6; int k = r % 5; int c = r / 5;
        float v = w1[(f * 64 + c) * 5 + k];
        d_w1u[i] = pack2(v, v);
    }
    for (int i = t0; i < 64 * 3 * 64; i += stride) {
        int f = i & 63; int r = i >> 6; int k = r % 3; int c = r / 3;
        d_w2t[i] = w2[(f * 64 + c) * 3 + k];
    }
    for (int i = t0; i < 16 * HC; i += stride) {
        int j = i & (HC - 1); int kq = i >> 7;
        ulonglong2 u;
        u.x = pack2(gw0[(4 * kq) * HC + j], gw0[(4 * kq + 1) * HC + j]);
        u.y = pack2(gw0[(4 * kq + 2) * HC + j], gw0[(4 * kq + 3) * HC + j]);
        d_gw0u[i] = u;
    }
    for (int i = t0; i < 32 * HC; i += stride) {
        int j = i & (HC - 1); int kq = i >> 7;
        ulonglong2 u, v;
        u.x = pack2(gw1[(4 * kq) * HC + j], gw1[(4 * kq + 1) * HC + j]);
        u.y = pack2(gw1[(4 * kq + 2) * HC + j], gw1[(4 * kq + 3) * HC + j]);
        d_gw1u[i] = u;
        v.x = pack2(gw2[(4 * kq) * HC + j], gw2[(4 * kq + 1) * HC + j]);
        v.y = pack2(gw2[(4 * kq + 2) * HC + j], gw2[(4 * kq + 3) * HC + j]);
        d_gw2u[i] = v;
    }
}

// ---------------- K1: edges ----------------
__global__ void __launch_bounds__(1024) k_edges(
        const float* __restrict__ ef, const int* __restrict__ ei,
        const float* __restrict__ eww, const float* __restrict__ ewb,
        float* __restrict__ out) {
    int w = threadIdx.x >> 5;
    int l = threadIdx.x & 31;
    int i0 = blockIdx.x * 32;
    int g0 = blockIdx.y * 32;
    __shared__ float ts[32][33];

    int g = g0 + w;
    int i = i0 + l;
    float v = 0.f;
    if (i < EPG) {
        int e = g * EPG + i;
        v = tanhf(fmaf(ef[e * 3 + 0], eww[0],
                 fmaf(ef[e * 3 + 1], eww[1],
                 fmaf(ef[e * 3 + 2], eww[2], ewb[0]))));
        int s = ei[e];
        int d = ei[NE + e];
        int g2 = d / NPG;
        int dl = d - g2 * NPG;
        int sl = s - g2 * NPG;
        d_At[(g2 * 64 + sl) * 64 + dl] = v;
    }
    ts[w][l] = v;
    __syncthreads();
    int iw = i0 + w;
    if (iw < EPG) out[NB * 4 + iw * NB + g0 + l] = ts[l][w];
}

// ---------------- K2: conv pipeline, one block per node, 64 threads ----------------
// conv1 reads the pooled conv0 output from TWO pre-paired smem layouts:
//   pe[f][m] = (P[2m-2], P[2m-1])  m=0..12   (taps k=0,2,4 at pe[j],pe[j+1],pe[j+2])
//   po[f][m] = (P[2m-1], P[2m])    m=0..11   (taps k=1,3 at po[j],po[j+1])
__global__ void __launch_bounds__(64) k_conv(
        const float* __restrict__ x,
        const float* __restrict__ w0, const float* __restrict__ b0,
        const float* __restrict__ b1, const float* __restrict__ b2) {
    int n = blockIdx.x;
    int f = threadIdx.x;
    __shared__ __align__(16) float xs[LQ];
    __shared__ __align__(16) ull   pes[64][13];
    __shared__ __align__(16) float pof[64][24];
    __shared__ float p1s[64][3];

    for (int i = f; i < LQ; i += 64) xs[i] = x[n * LQ + i];
    float w0r[7];
#pragma unroll
    for (int k = 0; k < 7; k++) w0r[k] = w0[f * 7 + k];
    ull w0d[7];
#pragma unroll
    for (int k = 0; k < 7; k++) w0d[k] = pack2(w0r[k], w0r[k]);
    float b0r = b0[f];
    ull b0d = pack2(b0r, b0r);
    // border zeros
    pes[f][0] = 0ull;
    pes[f][12] = 0ull;
    pof[f][0] = 0.f;
    pof[f][23] = 0.f;
    __syncthreads();

    // conv0 (k=7) + relu + maxpool7; window-pair f32x2 (outputs t=2jp, 2jp+1)
#pragma unroll 1
    for (int jp = 0; jp < 11; jp++) {
        const float2* xr = reinterpret_cast<const float2*>(&xs[14 * jp]);
        float a[20];
#pragma unroll
        for (int m = 0; m < 10; m++) { float2 t = xr[m]; a[2 * m] = t.x; a[2 * m + 1] = t.y; }
        ull xq[13];
#pragma unroll
        for (int l = 0; l < 13; l++) xq[l] = pack2(a[l], a[l + 7]);
        ull s[7];
#pragma unroll
        for (int u = 0; u < 7; u++) s[u] = b0d;
#pragma unroll
        for (int k = 0; k < 7; k++)
#pragma unroll
            for (int u = 0; u < 7; u++) s[u] = fma2(xq[u + k], w0d[k], s[u]);
        float m0 = -1e30f, m1 = -1e30f;
#pragma unroll
        for (int u = 0; u < 7; u++) {
            float2 v = u2f(s[u]);
            m0 = fmaxf(m0, v.x); m1 = fmaxf(m1, v.y);
        }
        m0 = fmaxf(m0, 0.f);
        m1 = fmaxf(m1, 0.f);
        pes[f][jp + 1] = pack2(m0, m1);
        pof[f][2 * jp + 1] = m0;
        pof[f][2 * jp + 2] = m1;
    }
    __syncthreads();

    // conv1 (k=5, pad 2): pure LDS.64 + FFMA2
    float b1r = b1[f];
    ull acc2[11];
#pragma unroll
    for (int j = 0; j < 11; j++) acc2[j] = pack2(b1r, b1r);

#pragma unroll 2
    for (int c = 0; c < 64; c++) {
        ull pe[13];
#pragma unroll
        for (int m = 0; m < 13; m++) pe[m] = pes[c][m];
        ull po[12];
        const ull* pou = reinterpret_cast<const ull*>(&pof[c][0]);
#pragma unroll
        for (int m = 0; m < 12; m++) po[m] = pou[m];
        const ull* wp = &d_w1u[c * 5 * 64 + f];
        ull w0u = wp[0], w1u = wp[64], w2u = wp[128], w3u = wp[192], w4u = wp[256];
#pragma unroll
        for (int j = 0; j < 11; j++) {
            acc2[j] = fma2(pe[j],     w0u, acc2[j]);
            acc2[j] = fma2(po[j],     w1u, acc2[j]);
            acc2[j] = fma2(pe[j + 1], w2u, acc2[j]);
            acc2[j] = fma2(po[j + 1], w3u, acc2[j]);
            acc2[j] = fma2(pe[j + 2], w4u, acc2[j]);
        }
    }
    float acc[22];
#pragma unroll
    for (int j = 0; j < 11; j++) {
        float2 v = u2f(acc2[j]);
        acc[2 * j] = v.x; acc[2 * j + 1] = v.y;
    }
#pragma unroll
    for (int j = 0; j < 3; j++) {
        float m = acc[7 * j];
#pragma unroll
        for (int u = 1; u < 7; u++) m = fmaxf(m, acc[7 * j + u]);
        p1s[f][j] = fmaxf(m, 0.f);
    }
    __syncthreads();

    // conv2 (k=3, len 3 -> 1)
    float s = b2[f];
#pragma unroll 1
    for (int c = 0; c < 64; c++) {
#pragma unroll
        for (int k = 0; k < 3; k++) s = fmaf(p1s[c][k], d_w2t[(c * 3 + k) * 64 + f], s);
    }
    d_H0[n * NF + f] = s;
}

// ---------------- BN1 stats ----------------
__global__ void __launch_bounds__(256) k_bns1a() {
    int t = threadIdx.x;
    int c = t & 63;
    int grp = t >> 6;
    int gid = blockIdx.x * 4 + grp;
    float s = 0.f, q = 0.f;
    for (int n = gid; n < NNODE; n += 244) {
        float v = d_H0[n * NF + c];
        s += v; q += v * v;
    }
    __shared__ float ss[256], sq[256];
    ss[t] = s; sq[t] = q;
    __syncthreads();
    if (t < 64) {
        d_bp1s[blockIdx.x * 64 + t] = ss[t] + ss[64 + t] + ss[128 + t] + ss[192 + t];
        d_bp1q[blockIdx.x * 64 + t] = sq[t] + sq[64 + t] + sq[128 + t] + sq[192 + t];
    }
}
__global__ void __launch_bounds__(64) k_bns1b(const float* __restrict__ gg,
                                              const float* __restrict__ bb) {
    int c = threadIdx.x;
    float s = 0.f, q = 0.f;
    for (int b = 0; b < 61; b++) { s += d_bp1s[b * 64 + c]; q += d_bp1q[b * 64 + c]; }
    float mean = s / (float)NNODE;
    float var = q / (float)NNODE - mean * mean;
    float rs = rsqrtf(var + 1e-5f);
    d_sc1[c] = gg[c] * rs;
    d_sh1[c] = bb[c] - mean * gg[c] * rs;
}
__global__ void __launch_bounds__(128) k_bns2b(const float* __restrict__ gg,
                                               const float* __restrict__ bb) {
    int c = threadIdx.x;
    float s = 0.f, q = 0.f;
    for (int g = 0; g < 2 * NB; g++) { s += d_bp2s[g * HC + c]; q += d_bp2q[g * HC + c]; }
    float mean = s / (float)NNODE;
    float var = q / (float)NNODE - mean * mean;
    float rs = rsqrtf(var + 1e-5f);
    d_sc2[c] = gg[c] * rs;
    d_sh2[c] = bb[c] - mean * gg[c] * rs;
}

// ---------------- GNN phase A: hw = bn?(h) @ W + b. grid (NB, 2), 128 thr ----------------
template<int K, bool BN, int INSEL, int WSEL>
__global__ void __launch_bounds__(128) k_gnn_a(const float* __restrict__ bias) {
    const float* hin = (INSEL == 0) ? (const float*)d_H0
                     : (INSEL == 1) ? (const float*)d_G1 : (const float*)d_G2;
    const ulonglong2* Wu = (WSEL == 0) ? (const ulonglong2*)d_gw0u
                         : (WSEL == 1) ? (const ulonglong2*)d_gw1u : (const ulonglong2*)d_gw2u;
    int g = blockIdx.x;
    int half = blockIdx.y;
    int n0 = half ? 31 : 0;
    int NR = half ? 30 : 31;
    int j = threadIdx.x;
    __shared__ __align__(16) float hs[31 * K];

    for (int idx = j; idx < NR * K; idx += 128) {
        float v = hin[(g * 61 + n0) * K + idx];
        if (BN) { int c = idx & (K - 1); v = fmaf(v, d_sc1[c], d_sh1[c]); }
        hs[idx] = v;
    }
    __syncthreads();

    ull acc[31];
#pragma unroll
    for (int n = 0; n < 31; n++) acc[n] = 0ull;
#pragma unroll 1
    for (int kq = 0; kq < K / 4; kq++) {
        ulonglong2 w = Wu[kq * HC + j];
#pragma unroll
        for (int n = 0; n < 31; n++) {
            ulonglong2 h2 = *reinterpret_cast<const ulonglong2*>(&hs[n * K + 4 * kq]);
            acc[n] = fma2(h2.x, w.x, acc[n]);
            acc[n] = fma2(h2.y, w.y, acc[n]);
        }
    }
    float bj = bias[j];
    for (int n = 0; n < NR; n++) {
        float2 v = u2f(acc[n]);
        d_HW[(g * 61 + n0 + n) * HC + j] = bj + v.x + v.y;
    }
}

// ---------------- GNN phase B: h' = A @ hw. grid (NB, 2), 128 thr ----------------
template<bool RELU, bool STATS, int OUTSEL>
__global__ void __launch_bounds__(128) k_gnn_b() {
    float* hout = (OUTSEL == 1) ? (float*)d_G1 : (float*)d_G2;
    int g = blockIdx.x;
    int half = blockIdx.y;
    int doff = half * 32;
    int ND = half ? 29 : 32;
    int j = threadIdx.x;
    __shared__ __align__(16) float hs[61 * HC];
    __shared__ __align__(16) float As2[61 * 36];

    for (int idx = j; idx < 61 * HC; idx += 128) hs[idx] = d_HW[g * 61 * HC + idx];
    for (int idx = j; idx < 61 * 32; idx += 128) {
        int s = idx >> 5, dd = idx & 31;
        As2[s * 36 + dd] = d_At[g * 4096 + s * 64 + doff + dd];
    }
    __syncthreads();

    ull acc[16];
#pragma unroll
    for (int p = 0; p < 16; p++) acc[p] = 0ull;
#pragma unroll 1
    for (int s = 0; s < 61; s++) {
        float v = hs[s * HC + j];
        ull v2 = pack2(v, v);
        const ulonglong2* ar = reinterpret_cast<const ulonglong2*>(&As2[s * 36]);
#pragma unroll
        for (int p = 0; p < 8; p++) {
            ulonglong2 a = ar[p];
            acc[2 * p]     = fma2(a.x, v2, acc[2 * p]);
            acc[2 * p + 1] = fma2(a.y, v2, acc[2 * p + 1]);
        }
    }
    float ssum = 0.f, sqsum = 0.f;
#pragma unroll
    for (int p = 0; p < 16; p++) {
        float2 r2 = u2f(acc[p]);
        int d0 = 2 * p, d1 = 2 * p + 1;
        if (d0 < ND) {
            float r = r2.x;
            if (STATS) { ssum += r; sqsum += r * r; }
            if (RELU) r = fmaxf(r, 0.f);
            hout[(g * 61 + doff + d0) * HC + j] = r;
        }
        if (d1 < ND) {
            float r = r2.y;
            if (STATS) { ssum += r; sqsum += r * r; }
            if (RELU) r = fmaxf(r, 0.f);
            hout[(g * 61 + doff + d1) * HC + j] = r;
        }
    }
    if (STATS) {
        d_bp2s[(g * 2 + half) * HC + j] = ssum;
        d_bp2q[(g * 2 + half) * HC + j] = sqsum;
    }
}

// ---------------- lin0: split-K over nodes. grid (61, 8), 128 thr ----------------
__global__ void __launch_bounds__(128) k_lin0(const float* __restrict__ W0) {
    int node = blockIdx.x;
    int gc = blockIdx.y;
    int j = threadIdx.x;
    __shared__ __align__(16) float vsT[HC * 20];
    float sc = d_sc2[j], sh = d_sh2[j];
#pragma unroll 1
    for (int q = 0; q < 16; q++) {
        int g = gc * 16 + q;
        vsT[j * 20 + q] = fmaf(d_G1[(g * 61 + node) * HC + j], sc, sh);
    }
    __syncthreads();
    ull acc[8];
#pragma unroll
    for (int p = 0; p < 8; p++) acc[p] = 0ull;
#pragma unroll 1
    for (int ch = 0; ch < HC; ch++) {
        float w = W0[(node * HC + ch) * HC + j];
        ull wd = pack2(w, w);
        const ulonglong2* vr = reinterpret_cast<const ulonglong2*>(&vsT[ch * 20]);
#pragma unroll
        for (int p = 0; p < 4; p++) {
            ulonglong2 v = vr[p];
            acc[2 * p]     = fma2(v.x, wd, acc[2 * p]);
            acc[2 * p + 1] = fma2(v.y, wd, acc[2 * p + 1]);
        }
    }
#pragma unroll
    for (int p = 0; p < 8; p++) {
        float2 v = u2f(acc[p]);
        int g0 = gc * 16 + 2 * p;
        d_P[(g0 * NPG + node) * HC + j] = v.x;
        d_P[((g0 + 1) * NPG + node) * HC + j] = v.y;
    }
}

// ---------------- head ----------------
__global__ void __launch_bounds__(128) k_head(const float* __restrict__ b0,
                                              const float* __restrict__ W1,
                                              const float* __restrict__ b1,
                                              const float* __restrict__ W2,
                                              const float* __restrict__ b2,
                                              float* __restrict__ out) {
    int g = blockIdx.x;
    int j = threadIdx.x;
    float z = b0[j];
    for (int node = 0; node < NPG; node++) z += d_P[(g * NPG + node) * HC + j];
    z = fmaxf(z, 0.f);
    __shared__ float z1[HC];
    z1[j] = z;
    __syncthreads();
    float a = b1[j];
    for (int k = 0; k < HC; k++) a = fmaf(z1[k], W1[k * HC + j], a);
    a = fmaxf(a, 0.f);
    __shared__ float z2[HC];
    z2[j] = a;
    __syncthreads();
    __shared__ float z3[4];
    if (j < 4) {
        float s = b2[j];
        for (int k = 0; k < HC; k++) s = fmaf(z2[k], W2[k * 4 + j], s);
        z3[j] = s;
    }
    __syncthreads();
    if (j == 0) {
        float m = fmaxf(fmaxf(z3[0], z3[1]), fmaxf(z3[2], z3[3]));
        float se = 0.f;
        for (int i = 0; i < 4; i++) se += expf(z3[i] - m);
        float l = logf(se);
        for (int i = 0; i < 4; i++) out[g * 4 + i] = z3[i] - m - l;
    }
}

// ---------------- launch ----------------
extern "C" void kernel_launch(void* const* d_in, const int* in_sizes, int n_in,
                              void* d_out, int out_size) {
    const float* x    = (const float*)d_in[0];
    const int*   ei   = (const int*)d_in[1];
    const float* ef   = (const float*)d_in[3];
    const float* cw0  = (const float*)d_in[4];
    const float* cb0  = (const float*)d_in[5];
    const float* cw1  = (const float*)d_in[6];
    const float* cb1  = (const float*)d_in[7];
    const float* cw2  = (const float*)d_in[8];
    const float* cb2  = (const float*)d_in[9];
    const float* bn1g = (const float*)d_in[10];
    const float* bn1b = (const float*)d_in[11];
    const float* gw0  = (const float*)d_in[12];
    const float* gb0  = (const float*)d_in[13];
    const float* gw1  = (const float*)d_in[14];
    const float* gb1  = (const float*)d_in[15];
    const float* gw2  = (const float*)d_in[16];
    const float* gb2  = (const float*)d_in[17];
    const float* bn2g = (const float*)d_in[18];
    const float* bn2b = (const float*)d_in[19];
    const float* lw0  = (const float*)d_in[20];
    const float* lb0  = (const float*)d_in[21];
    const float* lw1  = (const float*)d_in[22];
    const float* lb1  = (const float*)d_in[23];
    const float* lw2  = (const float*)d_in[24];
    const float* lb2  = (const float*)d_in[25];
    const float* eww  = (const float*)d_in[26];
    const float* ewb  = (const float*)d_in[27];
    float* out = (float*)d_out;

    // Launch order arranged so k_conv is launch #4 (ncu capture slot).
    k_prep_zero<<<256, 256>>>();
    k_prep_w<<<256, 256>>>(cw1, cw2, gw0, gw1, gw2);
    dim3 eg((EPG + 31) / 32, NB / 32);
    k_edges<<<eg, 1024>>>(ef, ei, eww, ewb, out);
    k_conv<<<NNODE, 64>>>(x, cw0, cb0, cb1, cb2);
    k_bns1a<<<61, 256>>>();
    k_bns1b<<<1, 64>>>(bn1g, bn1b);
    dim3 gg(NB, 2);
    k_gnn_a< 64, true,  0, 0><<<gg, 128>>>(gb0);
    k_gnn_b<true,  false, 1><<<gg, 128>>>();
    k_gnn_a<128, false, 1, 1><<<gg, 128>>>(gb1);
    k_gnn_b<true,  false, 2><<<gg, 128>>>();
    k_gnn_a<128, false, 2, 2><<<gg, 128>>>(gb2);
    k_gnn_b<false, true,  1><<<gg, 128>>>();
    k_bns2b<<<1, 128>>>(bn2g, bn2b);
    dim3 lg(NPG, 8);
    k_lin0<<<lg, 128>>>(lw0);
    k_head<<<NB, 128>>>(lb0, lw1, lb1, lw2, lb2, out);
}